// round 1
// baseline (speedup 1.0000x reference)
#include <cuda_runtime.h>
#include <cstdint>

#define V 12288
#define CIN 16
#define COUT 32
#define KORD 5
#define CU 512          // u-chunk staged in smem
#define VT 32           // v rows per CTA
#define CV (CIN * V)

// Scratch for T1..T4 (T0 == x read directly). 4 * 16 * 12288 * 4B = 3.1 MB.
__device__ float g_T[4 * CV];

__device__ __forceinline__ unsigned long long pack2(float x) {
    unsigned long long r;
    unsigned xi = __float_as_uint(x);
    asm("mov.b64 %0, {%1, %2};" : "=l"(r) : "r"(xi), "r"(xi));
    return r;
}

__device__ __forceinline__ unsigned long long fma2(unsigned long long a,
                                                   unsigned long long b,
                                                   unsigned long long c) {
    unsigned long long d;
    asm("fma.rn.f32x2 %0, %1, %2, %3;" : "=l"(d) : "l"(a), "l"(b), "l"(c));
    return d;
}

// O[i][v] = alpha * sum_u A[i][u] * L[v][u] + beta * P[i][v]
// A,P,O: [CIN][V] row-major. L: [V][V] row-major.
__global__ __launch_bounds__(256, 2)
void cheb_pass(const float* __restrict__ A,
               const float* __restrict__ L,
               const float* __restrict__ P,
               float* __restrict__ O,
               float alpha, float beta)
{
    // As[j][u'] = (A[2j][u0+u'], A[2j+1][u0+u'])  -> LDS.64 feeds fma.f32x2
    __shared__ float2 As[8][CU];

    const int tid  = threadIdx.x;
    const int w    = tid >> 5;
    const int lane = tid & 31;
    const int vbase = blockIdx.x * VT;
    const int v0 = vbase + 4 * w;

    const float* Lr0 = L + (size_t)(v0 + 0) * V;
    const float* Lr1 = L + (size_t)(v0 + 1) * V;
    const float* Lr2 = L + (size_t)(v0 + 2) * V;
    const float* Lr3 = L + (size_t)(v0 + 3) * V;

    unsigned long long acc[8][4];
#pragma unroll
    for (int j = 0; j < 8; j++)
#pragma unroll
        for (int vv = 0; vv < 4; vv++) acc[j][vv] = 0ULL;

    for (int u0 = 0; u0 < V; u0 += CU) {
        __syncthreads();
        // Stage: warp w stages rows 2w, 2w+1 as interleaved pairs.
        {
            const float* a0 = A + (size_t)(2 * w) * V + u0;
            const float* a1 = a0 + V;
#pragma unroll
            for (int kk = 0; kk < CU / 32; kk++) {
                int up = lane + 32 * kk;
                As[w][up] = make_float2(a0[up], a1[up]);
            }
        }
        __syncthreads();

#pragma unroll 4
        for (int t = 0; t < CU / 32; t++) {
            const int up = lane + 32 * t;
            const int ug = u0 + up;
            float l0 = __ldcs(Lr0 + ug);
            float l1 = __ldcs(Lr1 + ug);
            float l2 = __ldcs(Lr2 + ug);
            float l3 = __ldcs(Lr3 + ug);
            unsigned long long b0 = pack2(l0);
            unsigned long long b1 = pack2(l1);
            unsigned long long b2 = pack2(l2);
            unsigned long long b3 = pack2(l3);
#pragma unroll
            for (int j = 0; j < 8; j++) {
                unsigned long long a =
                    *reinterpret_cast<const unsigned long long*>(&As[j][up]);
                acc[j][0] = fma2(a, b0, acc[j][0]);
                acc[j][1] = fma2(a, b1, acc[j][1]);
                acc[j][2] = fma2(a, b2, acc[j][2]);
                acc[j][3] = fma2(a, b3, acc[j][3]);
            }
        }
    }

    // Cross-lane reduce (lanes were partial sums over u) + fused recurrence epilogue.
#pragma unroll
    for (int j = 0; j < 8; j++) {
#pragma unroll
        for (int vv = 0; vv < 4; vv++) {
            unsigned lo_u, hi_u;
            asm("mov.b64 {%0, %1}, %2;" : "=r"(lo_u), "=r"(hi_u) : "l"(acc[j][vv]));
            float lo = __uint_as_float(lo_u);
            float hi = __uint_as_float(hi_u);
#pragma unroll
            for (int off = 16; off; off >>= 1) {
                lo += __shfl_xor_sync(0xFFFFFFFFu, lo, off);
                hi += __shfl_xor_sync(0xFFFFFFFFu, hi, off);
            }
            if (lane == (j * 4 + vv)) {
                const int v = v0 + vv;
                const int i0 = 2 * j;
                float r0 = alpha * lo;
                float r1 = alpha * hi;
                if (beta != 0.0f) {
                    r0 += beta * P[(size_t)i0 * V + v];
                    r1 += beta * P[(size_t)(i0 + 1) * V + v];
                }
                O[(size_t)i0 * V + v]       = r0;
                O[(size_t)(i0 + 1) * V + v] = r1;
            }
        }
    }
}

// out[o][v] = bias[o] + sum_k sum_i T_k[i][v] * W[k][i][o]
__global__ __launch_bounds__(128)
void cheb_combine(const float* __restrict__ x,
                  const float* __restrict__ Wt,
                  const float* __restrict__ bias,
                  float* __restrict__ out)
{
    __shared__ float Ws[KORD * CIN * COUT];
    __shared__ float bs[COUT];
    const int tid = threadIdx.x;
    for (int idx = tid; idx < KORD * CIN * COUT; idx += blockDim.x) Ws[idx] = Wt[idx];
    if (tid < COUT) bs[tid] = bias[tid];
    __syncthreads();

    const int v = blockIdx.x * blockDim.x + tid;

    float acc[COUT];
#pragma unroll
    for (int o = 0; o < COUT; o++) acc[o] = bs[o];

#pragma unroll
    for (int k = 0; k < KORD; k++) {
        const float* T = (k == 0) ? x : (g_T + (size_t)(k - 1) * CV);
#pragma unroll
        for (int i = 0; i < CIN; i++) {
            float tv = T[(size_t)i * V + v];
            const float* wrow = &Ws[(k * CIN + i) * COUT];
#pragma unroll
            for (int o = 0; o < COUT; o++) acc[o] = fmaf(tv, wrow[o], acc[o]);
        }
    }
#pragma unroll
    for (int o = 0; o < COUT; o++) out[(size_t)o * V + v] = acc[o];
}

extern "C" void kernel_launch(void* const* d_in, const int* in_sizes, int n_in,
                              void* d_out, int out_size)
{
    const float* x  = (const float*)d_in[0];
    const float* L  = (const float*)d_in[1];
    const float* Wt = (const float*)d_in[2];
    const float* b  = (const float*)d_in[3];
    float* out = (float*)d_out;

    float* gT = nullptr;
    cudaGetSymbolAddress((void**)&gT, g_T);

    const dim3 grid(V / VT);   // 384 CTAs
    const dim3 blk(256);

    // T1 = x @ L^T
    cheb_pass<<<grid, blk>>>(x, L, x, gT + 0 * CV, 1.0f, 0.0f);
    // T2 = 2 T1 @ L^T - x
    cheb_pass<<<grid, blk>>>(gT + 0 * CV, L, x, gT + 1 * CV, 2.0f, -1.0f);
    // T3 = 2 T2 @ L^T - T1
    cheb_pass<<<grid, blk>>>(gT + 1 * CV, L, gT + 0 * CV, gT + 2 * CV, 2.0f, -1.0f);
    // T4 = 2 T3 @ L^T - T2
    cheb_pass<<<grid, blk>>>(gT + 2 * CV, L, gT + 1 * CV, gT + 3 * CV, 2.0f, -1.0f);
    // out = einsum + bias
    cheb_combine<<<V / 128, 128>>>(x, Wt, b, out);
}